// round 1
// baseline (speedup 1.0000x reference)
#include <cuda_runtime.h>

#define E_TOTAL 1000000
#define FX      32
#define D0      96
#define HID     64
#define OUTC    32
#define KL2     160
#define THREADS 512
#define TILE_E  128
#define ESTR    132            // TILE_E + 4: keeps row bases 16B-aligned
#define NTILES  ((E_TOTAL + TILE_E - 1) / TILE_E)
#define GRID    152
#define LN_EPS  1e-5f

typedef unsigned long long u64;

// ---- packed f32x2 helpers (sm_103a FFMA2 path, PTX-only per SASS_QUICKREF) ----
__device__ __forceinline__ u64 pack2(float x, float y) {
    u64 r;
    asm("mov.b64 %0, {%1, %2};" : "=l"(r) : "r"(__float_as_uint(x)), "r"(__float_as_uint(y)));
    return r;
}
__device__ __forceinline__ u64 dup2(float x) {
    u64 r;
    unsigned u = __float_as_uint(x);
    asm("mov.b64 %0, {%1, %2};" : "=l"(r) : "r"(u), "r"(u));
    return r;
}
__device__ __forceinline__ void fma2(u64 &d, u64 a, u64 b) {
    asm("fma.rn.f32x2 %0, %1, %2, %3;" : "=l"(d) : "l"(a), "l"(b), "l"(d));
}
__device__ __forceinline__ void unpack2(u64 v, float &x, float &y) {
    unsigned lo, hi;
    asm("mov.b64 {%0, %1}, %2;" : "=r"(lo), "=r"(hi) : "l"(v));
    x = __uint_as_float(lo);
    y = __uint_as_float(hi);
}

__device__ __forceinline__ void cp4(float* dst, const float* src, int n, int tid) {
    float4* d4 = (float4*)dst;
    const float4* s4 = (const float4*)src;
    for (int i = tid; i < (n >> 2); i += THREADS) d4[i] = s4[i];
}

// relu -> LayerNorm(64) -> transposed store into xs rows [rowBase + c0 .. +3]
__device__ __forceinline__ void relu_ln_store(
    u64 acc[4][2], const float* __restrict__ bias, const float* __restrict__ gamma,
    const float* __restrict__ beta, float* __restrict__ xs,
    int rowBase, int e0, int c0)
{
    float v[4][4];
#pragma unroll
    for (int e = 0; e < 4; e++) {
        unpack2(acc[e][0], v[e][0], v[e][1]);
        unpack2(acc[e][1], v[e][2], v[e][3]);
    }
    float b0 = bias[c0], b1 = bias[c0 + 1], b2 = bias[c0 + 2], b3 = bias[c0 + 3];
    float s[4], q[4];
#pragma unroll
    for (int e = 0; e < 4; e++) {
        float t0 = fmaxf(v[e][0] + b0, 0.f);
        float t1 = fmaxf(v[e][1] + b1, 0.f);
        float t2 = fmaxf(v[e][2] + b2, 0.f);
        float t3 = fmaxf(v[e][3] + b3, 0.f);
        v[e][0] = t0; v[e][1] = t1; v[e][2] = t2; v[e][3] = t3;
        s[e] = t0 + t1 + t2 + t3;
        q[e] = t0 * t0 + t1 * t1 + t2 * t2 + t3 * t3;
    }
    // 16 threads (same lane%16 group) share one edge's 64 channels
#pragma unroll
    for (int m = 1; m < 16; m <<= 1) {
#pragma unroll
        for (int e = 0; e < 4; e++) {
            s[e] += __shfl_xor_sync(0xffffffffu, s[e], m);
            q[e] += __shfl_xor_sync(0xffffffffu, q[e], m);
        }
    }
    float gm[4] = {gamma[c0], gamma[c0 + 1], gamma[c0 + 2], gamma[c0 + 3]};
    float bt[4] = {beta[c0], beta[c0 + 1], beta[c0 + 2], beta[c0 + 3]};
#pragma unroll
    for (int e = 0; e < 4; e++) {
        float mean = s[e] * (1.f / 64.f);
        float var  = q[e] * (1.f / 64.f) - mean * mean;
        float rstd = rsqrtf(var + LN_EPS);
#pragma unroll
        for (int c = 0; c < 4; c++)
            v[e][c] = (v[e][c] - mean) * rstd * gm[c] + bt[c];
    }
#pragma unroll
    for (int c = 0; c < 4; c++) {
        *(float4*)&xs[(rowBase + c0 + c) * ESTR + e0] =
            make_float4(v[0][c], v[1][c], v[2][c], v[3][c]);
    }
}

__global__ __launch_bounds__(THREADS, 1)
void EdgeModel_48636209660177_kernel(
    const float* __restrict__ src, const float* __restrict__ dst,
    const float* __restrict__ ea,
    const float* __restrict__ W1, const float* __restrict__ b1,
    const float* __restrict__ g1, const float* __restrict__ be1,
    const float* __restrict__ W2, const float* __restrict__ b2,
    const float* __restrict__ g2, const float* __restrict__ be2,
    const float* __restrict__ W3, const float* __restrict__ b3,
    float* __restrict__ out)
{
    extern __shared__ float sm[];
    float* sW1  = sm;                 // 96*64 = 6144
    float* sW2  = sW1 + 6144;         // 160*64 = 10240
    float* sW3  = sW2 + 10240;        // 64*32 = 2048
    float* sb1  = sW3 + 2048;
    float* sg1  = sb1 + 64;
    float* sbe1 = sg1 + 64;
    float* sb2  = sbe1 + 64;
    float* sg2  = sb2 + 64;
    float* sbe2 = sg2 + 64;
    float* sb3  = sbe2 + 64;          // 32
    float* xs   = sb3 + 32;           // 160 rows * ESTR

    const int tid = threadIdx.x;
    cp4(sW1, W1, 6144, tid);
    cp4(sW2, W2, 10240, tid);
    cp4(sW3, W3, 2048, tid);
    cp4(sb1, b1, 64, tid);  cp4(sg1, g1, 64, tid);  cp4(sbe1, be1, 64, tid);
    cp4(sb2, b2, 64, tid);  cp4(sg2, g2, 64, tid);  cp4(sbe2, be2, 64, tid);
    cp4(sb3, b3, 32, tid);

    const int eg = tid >> 4;    // 0..31 -> 4 edges each
    const int cg = tid & 15;    // 0..15 -> 4 cols each (layers 1/2), 2 cols (layer 3)
    const int e0 = eg * 4;
    const int c0 = cg * 4;

    for (int tile = blockIdx.x; tile < NTILES; tile += gridDim.x) {
        const int ebase = tile * TILE_E;
        __syncthreads();   // protect xs rows 64..127 from previous tile's layer-3 reads

        // ---- stage x0 = concat(src,dest,edge_attr) transposed into rows 64..159 ----
#pragma unroll
        for (int t = 0; t < 3; t++) {
            const float* g = (t == 0) ? src : (t == 1) ? dst : ea;
            const int R = 64 + t * 32;
            for (int i = tid; i < TILE_E * 8; i += THREADS) {
                int e = i >> 3, c4 = (i & 7) * 4;
                float4 v = make_float4(0.f, 0.f, 0.f, 0.f);
                if (ebase + e < E_TOTAL)
                    v = *(const float4*)&g[(size_t)(ebase + e) * FX + c4];
                xs[(R + c4 + 0) * ESTR + e] = v.x;
                xs[(R + c4 + 1) * ESTR + e] = v.y;
                xs[(R + c4 + 2) * ESTR + e] = v.z;
                xs[(R + c4 + 3) * ESTR + e] = v.w;
            }
        }
        __syncthreads();

        // ---- layer 1: h1 = LN(relu(x0 @ W1 + b1)) -> rows 0..63 ----
        {
            u64 acc[4][2];
#pragma unroll
            for (int e = 0; e < 4; e++) { acc[e][0] = 0ull; acc[e][1] = 0ull; }
#pragma unroll 4
            for (int k = 0; k < D0; k++) {
                float4 xv = *(const float4*)&xs[(64 + k) * ESTR + e0];
                float4 wv = *(const float4*)&sW1[k * HID + c0];
                u64 w0 = pack2(wv.x, wv.y), w1 = pack2(wv.z, wv.w);
                u64 a;
                a = dup2(xv.x); fma2(acc[0][0], a, w0); fma2(acc[0][1], a, w1);
                a = dup2(xv.y); fma2(acc[1][0], a, w0); fma2(acc[1][1], a, w1);
                a = dup2(xv.z); fma2(acc[2][0], a, w0); fma2(acc[2][1], a, w1);
                a = dup2(xv.w); fma2(acc[3][0], a, w0); fma2(acc[3][1], a, w1);
            }
            relu_ln_store(acc, sb1, sg1, sbe1, xs, 0, e0, c0);
        }
        __syncthreads();

        // ---- layer 2: h2 = LN(relu(concat(h1,x0) @ W2 + b2)) -> rows 64..127 ----
        {
            u64 acc[4][2];
#pragma unroll
            for (int e = 0; e < 4; e++) { acc[e][0] = 0ull; acc[e][1] = 0ull; }
#pragma unroll 4
            for (int k = 0; k < KL2; k++) {
                float4 xv = *(const float4*)&xs[k * ESTR + e0];
                float4 wv = *(const float4*)&sW2[k * HID + c0];
                u64 w0 = pack2(wv.x, wv.y), w1 = pack2(wv.z, wv.w);
                u64 a;
                a = dup2(xv.x); fma2(acc[0][0], a, w0); fma2(acc[0][1], a, w1);
                a = dup2(xv.y); fma2(acc[1][0], a, w0); fma2(acc[1][1], a, w1);
                a = dup2(xv.z); fma2(acc[2][0], a, w0); fma2(acc[2][1], a, w1);
                a = dup2(xv.w); fma2(acc[3][0], a, w0); fma2(acc[3][1], a, w1);
            }
            __syncthreads();   // all reads of rows 0..159 done before overwriting 64..127
            relu_ln_store(acc, sb2, sg2, sbe2, xs, 64, e0, c0);
        }
        __syncthreads();

        // ---- layer 3: out = h2 @ W3 + b3 ----
        {
            const int c0b = cg * 2;
            u64 acc3[4] = {0ull, 0ull, 0ull, 0ull};
#pragma unroll 4
            for (int k = 0; k < HID; k++) {
                float4 xv = *(const float4*)&xs[(64 + k) * ESTR + e0];
                float2 wv = *(const float2*)&sW3[k * OUTC + c0b];
                u64 w = pack2(wv.x, wv.y);
                fma2(acc3[0], dup2(xv.x), w);
                fma2(acc3[1], dup2(xv.y), w);
                fma2(acc3[2], dup2(xv.z), w);
                fma2(acc3[3], dup2(xv.w), w);
            }
            float bx = sb3[c0b], by = sb3[c0b + 1];
#pragma unroll
            for (int e = 0; e < 4; e++) {
                int ge = ebase + e0 + e;
                if (ge < E_TOTAL) {
                    float x, y;
                    unpack2(acc3[e], x, y);
                    *(float2*)&out[(size_t)ge * OUTC + c0b] = make_float2(x + bx, y + by);
                }
            }
        }
    }
}

#define SMEM_BYTES ((6144 + 10240 + 2048 + 64*6 + 32 + 160*ESTR) * (int)sizeof(float))

extern "C" void kernel_launch(void* const* d_in, const int* in_sizes, int n_in,
                              void* d_out, int out_size) {
    (void)in_sizes; (void)n_in; (void)out_size;
    const float* src = (const float*)d_in[0];
    const float* dst = (const float*)d_in[1];
    const float* ea  = (const float*)d_in[2];
    const float* W1  = (const float*)d_in[3];
    const float* b1  = (const float*)d_in[4];
    const float* g1  = (const float*)d_in[5];
    const float* be1 = (const float*)d_in[6];
    const float* W2  = (const float*)d_in[7];
    const float* b2  = (const float*)d_in[8];
    const float* g2  = (const float*)d_in[9];
    const float* be2 = (const float*)d_in[10];
    const float* W3  = (const float*)d_in[11];
    const float* b3  = (const float*)d_in[12];
    float* out = (float*)d_out;

    cudaFuncSetAttribute(EdgeModel_48636209660177_kernel,
                         cudaFuncAttributeMaxDynamicSharedMemorySize, SMEM_BYTES);
    EdgeModel_48636209660177_kernel<<<GRID, THREADS, SMEM_BYTES>>>(
        src, dst, ea, W1, b1, g1, be1, W2, b2, g2, be2, W3, b3, out);
}

// round 2
// speedup vs baseline: 1.0435x; 1.0435x over previous
#include <cuda_runtime.h>

#define E_TOTAL 1000000
#define FX      32
#define D0      96
#define HID     64
#define OUTC    32
#define KL2     160
#define THREADS 512
#define TILE_E  128
#define ESTR    132            // TILE_E + 4: keeps row bases 16B-aligned
#define NTILES  ((E_TOTAL + TILE_E - 1) / TILE_E)
#define GRID    152
#define LN_EPS  1e-5f

typedef unsigned long long u64;

// ---- packed f32x2 helpers (sm_103a FFMA2 path, PTX-only per SASS_QUICKREF) ----
__device__ __forceinline__ u64 pack2(float x, float y) {
    u64 r;
    asm("mov.b64 %0, {%1, %2};" : "=l"(r) : "r"(__float_as_uint(x)), "r"(__float_as_uint(y)));
    return r;
}
__device__ __forceinline__ u64 dup2(float x) {
    u64 r;
    unsigned u = __float_as_uint(x);
    asm("mov.b64 %0, {%1, %2};" : "=l"(r) : "r"(u), "r"(u));
    return r;
}
__device__ __forceinline__ void fma2(u64 &d, u64 a, u64 b) {
    asm("fma.rn.f32x2 %0, %1, %2, %3;" : "=l"(d) : "l"(a), "l"(b), "l"(d));
}
__device__ __forceinline__ void unpack2(u64 v, float &x, float &y) {
    unsigned lo, hi;
    asm("mov.b64 {%0, %1}, %2;" : "=r"(lo), "=r"(hi) : "l"(v));
    x = __uint_as_float(lo);
    y = __uint_as_float(hi);
}

__device__ __forceinline__ void cp4(float* dst, const float* src, int n, int tid) {
    float4* d4 = (float4*)dst;
    const float4* s4 = (const float4*)src;
    for (int i = tid; i < (n >> 2); i += THREADS) d4[i] = s4[i];
}

// relu -> LayerNorm(64) -> transposed store into xs rows [rowBase + c0 .. +3]
__device__ __forceinline__ void relu_ln_store(
    u64 acc[4][2], const float* __restrict__ bias, const float* __restrict__ gamma,
    const float* __restrict__ beta, float* __restrict__ xs,
    int rowBase, int e0, int c0)
{
    float v[4][4];
#pragma unroll
    for (int e = 0; e < 4; e++) {
        unpack2(acc[e][0], v[e][0], v[e][1]);
        unpack2(acc[e][1], v[e][2], v[e][3]);
    }
    float b0 = bias[c0], b1 = bias[c0 + 1], b2 = bias[c0 + 2], b3 = bias[c0 + 3];
    float s[4], q[4];
#pragma unroll
    for (int e = 0; e < 4; e++) {
        float t0 = fmaxf(v[e][0] + b0, 0.f);
        float t1 = fmaxf(v[e][1] + b1, 0.f);
        float t2 = fmaxf(v[e][2] + b2, 0.f);
        float t3 = fmaxf(v[e][3] + b3, 0.f);
        v[e][0] = t0; v[e][1] = t1; v[e][2] = t2; v[e][3] = t3;
        s[e] = t0 + t1 + t2 + t3;
        q[e] = t0 * t0 + t1 * t1 + t2 * t2 + t3 * t3;
    }
    // 16 threads (same lane%16 group) share one edge's 64 channels
#pragma unroll
    for (int m = 1; m < 16; m <<= 1) {
#pragma unroll
        for (int e = 0; e < 4; e++) {
            s[e] += __shfl_xor_sync(0xffffffffu, s[e], m);
            q[e] += __shfl_xor_sync(0xffffffffu, q[e], m);
        }
    }
    float gm[4] = {gamma[c0], gamma[c0 + 1], gamma[c0 + 2], gamma[c0 + 3]};
    float bt[4] = {beta[c0], beta[c0 + 1], beta[c0 + 2], beta[c0 + 3]};
#pragma unroll
    for (int e = 0; e < 4; e++) {
        float mean = s[e] * (1.f / 64.f);
        float var  = q[e] * (1.f / 64.f) - mean * mean;
        float rstd = rsqrtf(var + LN_EPS);
#pragma unroll
        for (int c = 0; c < 4; c++)
            v[e][c] = (v[e][c] - mean) * rstd * gm[c] + bt[c];
    }
#pragma unroll
    for (int c = 0; c < 4; c++) {
        *(float4*)&xs[(rowBase + c0 + c) * ESTR + e0] =
            make_float4(v[0][c], v[1][c], v[2][c], v[3][c]);
    }
}

__global__ __launch_bounds__(THREADS, 1)
void EdgeModel_48636209660177_kernel(
    const float* __restrict__ src, const float* __restrict__ dst,
    const float* __restrict__ ea,
    const float* __restrict__ W1, const float* __restrict__ b1,
    const float* __restrict__ g1, const float* __restrict__ be1,
    const float* __restrict__ W2, const float* __restrict__ b2,
    const float* __restrict__ g2, const float* __restrict__ be2,
    const float* __restrict__ W3, const float* __restrict__ b3,
    float* __restrict__ out)
{
    extern __shared__ float sm[];
    float* sW1  = sm;                 // 96*64 = 6144
    float* sW2  = sW1 + 6144;         // 160*64 = 10240
    float* sW3  = sW2 + 10240;        // 64*32 = 2048
    float* sb1  = sW3 + 2048;
    float* sg1  = sb1 + 64;
    float* sbe1 = sg1 + 64;
    float* sb2  = sbe1 + 64;
    float* sg2  = sb2 + 64;
    float* sbe2 = sg2 + 64;
    float* sb3  = sbe2 + 64;          // 32
    float* xs   = sb3 + 32;           // 160 rows * ESTR

    const int tid = threadIdx.x;
    cp4(sW1, W1, 6144, tid);
    cp4(sW2, W2, 10240, tid);
    cp4(sW3, W3, 2048, tid);
    cp4(sb1, b1, 64, tid);  cp4(sg1, g1, 64, tid);  cp4(sbe1, be1, 64, tid);
    cp4(sb2, b2, 64, tid);  cp4(sg2, g2, 64, tid);  cp4(sbe2, be2, 64, tid);
    cp4(sb3, b3, 32, tid);

    const int eg = tid >> 4;    // 0..31 -> 4 edges each
    const int cg = tid & 15;    // 0..15 -> 4 cols each (layers 1/2), 2 cols (layer 3)
    const int e0 = eg * 4;
    const int c0 = cg * 4;

    for (int tile = blockIdx.x; tile < NTILES; tile += gridDim.x) {
        const int ebase = tile * TILE_E;
        __syncthreads();   // protect xs rows 64..127 from previous tile's layer-3 reads

        // ---- stage x0 = concat(src,dest,edge_attr) transposed into rows 64..159 ----
#pragma unroll
        for (int t = 0; t < 3; t++) {
            const float* g = (t == 0) ? src : (t == 1) ? dst : ea;
            const int R = 64 + t * 32;
            for (int i = tid; i < TILE_E * 8; i += THREADS) {
                int e = i >> 3, c4 = (i & 7) * 4;
                float4 v = make_float4(0.f, 0.f, 0.f, 0.f);
                if (ebase + e < E_TOTAL)
                    v = *(const float4*)&g[(size_t)(ebase + e) * FX + c4];
                xs[(R + c4 + 0) * ESTR + e] = v.x;
                xs[(R + c4 + 1) * ESTR + e] = v.y;
                xs[(R + c4 + 2) * ESTR + e] = v.z;
                xs[(R + c4 + 3) * ESTR + e] = v.w;
            }
        }
        __syncthreads();

        // ---- layer 1: h1 = LN(relu(x0 @ W1 + b1)) -> rows 0..63 ----
        {
            u64 acc[4][2];
#pragma unroll
            for (int e = 0; e < 4; e++) { acc[e][0] = 0ull; acc[e][1] = 0ull; }
#pragma unroll 4
            for (int k = 0; k < D0; k++) {
                float4 xv = *(const float4*)&xs[(64 + k) * ESTR + e0];
                float4 wv = *(const float4*)&sW1[k * HID + c0];
                u64 w0 = pack2(wv.x, wv.y), w1 = pack2(wv.z, wv.w);
                u64 a;
                a = dup2(xv.x); fma2(acc[0][0], a, w0); fma2(acc[0][1], a, w1);
                a = dup2(xv.y); fma2(acc[1][0], a, w0); fma2(acc[1][1], a, w1);
                a = dup2(xv.z); fma2(acc[2][0], a, w0); fma2(acc[2][1], a, w1);
                a = dup2(xv.w); fma2(acc[3][0], a, w0); fma2(acc[3][1], a, w1);
            }
            relu_ln_store(acc, sb1, sg1, sbe1, xs, 0, e0, c0);
        }
        __syncthreads();

        // ---- layer 2: h2 = LN(relu(concat(h1,x0) @ W2 + b2)) -> rows 64..127 ----
        {
            u64 acc[4][2];
#pragma unroll
            for (int e = 0; e < 4; e++) { acc[e][0] = 0ull; acc[e][1] = 0ull; }
#pragma unroll 4
            for (int k = 0; k < KL2; k++) {
                float4 xv = *(const float4*)&xs[k * ESTR + e0];
                float4 wv = *(const float4*)&sW2[k * HID + c0];
                u64 w0 = pack2(wv.x, wv.y), w1 = pack2(wv.z, wv.w);
                u64 a;
                a = dup2(xv.x); fma2(acc[0][0], a, w0); fma2(acc[0][1], a, w1);
                a = dup2(xv.y); fma2(acc[1][0], a, w0); fma2(acc[1][1], a, w1);
                a = dup2(xv.z); fma2(acc[2][0], a, w0); fma2(acc[2][1], a, w1);
                a = dup2(xv.w); fma2(acc[3][0], a, w0); fma2(acc[3][1], a, w1);
            }
            __syncthreads();   // all reads of rows 0..159 done before overwriting 64..127
            relu_ln_store(acc, sb2, sg2, sbe2, xs, 64, e0, c0);
        }
        __syncthreads();

        // ---- layer 3: out = h2 @ W3 + b3 ----
        {
            const int c0b = cg * 2;
            u64 acc3[4] = {0ull, 0ull, 0ull, 0ull};
#pragma unroll 4
            for (int k = 0; k < HID; k++) {
                float4 xv = *(const float4*)&xs[(64 + k) * ESTR + e0];
                float2 wv = *(const float2*)&sW3[k * OUTC + c0b];
                u64 w = pack2(wv.x, wv.y);
                fma2(acc3[0], dup2(xv.x), w);
                fma2(acc3[1], dup2(xv.y), w);
                fma2(acc3[2], dup2(xv.z), w);
                fma2(acc3[3], dup2(xv.w), w);
            }
            float bx = sb3[c0b], by = sb3[c0b + 1];
#pragma unroll
            for (int e = 0; e < 4; e++) {
                int ge = ebase + e0 + e;
                if (ge < E_TOTAL) {
                    float x, y;
                    unpack2(acc3[e], x, y);
                    *(float2*)&out[(size_t)ge * OUTC + c0b] = make_float2(x + bx, y + by);
                }
            }
        }
    }
}

#define SMEM_BYTES ((6144 + 10240 + 2048 + 64*6 + 32 + 160*ESTR) * (int)sizeof(float))

extern "C" void kernel_launch(void* const* d_in, const int* in_sizes, int n_in,
                              void* d_out, int out_size) {
    (void)in_sizes; (void)n_in; (void)out_size;
    const float* src = (const float*)d_in[0];
    const float* dst = (const float*)d_in[1];
    const float* ea  = (const float*)d_in[2];
    const float* W1  = (const float*)d_in[3];
    const float* b1  = (const float*)d_in[4];
    const float* g1  = (const float*)d_in[5];
    const float* be1 = (const float*)d_in[6];
    const float* W2  = (const float*)d_in[7];
    const float* b2  = (const float*)d_in[8];
    const float* g2  = (const float*)d_in[9];
    const float* be2 = (const float*)d_in[10];
    const float* W3  = (const float*)d_in[11];
    const float* b3  = (const float*)d_in[12];
    float* out = (float*)d_out;

    cudaFuncSetAttribute(EdgeModel_48636209660177_kernel,
                         cudaFuncAttributeMaxDynamicSharedMemorySize, SMEM_BYTES);
    EdgeModel_48636209660177_kernel<<<GRID, THREADS, SMEM_BYTES>>>(
        src, dst, ea, W1, b1, g1, be1, W2, b2, g2, be2, W3, b3, out);
}

// round 3
// speedup vs baseline: 1.0527x; 1.0088x over previous
#include <cuda_runtime.h>

#define E_TOTAL 1000000
#define FX      32
#define D0      96
#define HID     64
#define OUTC    32
#define KL2     160
#define THREADS 512
#define TILE_E  128
#define ESTR    132            // TILE_E + 4: keeps row bases 16B-aligned
#define NTILES  ((E_TOTAL + TILE_E - 1) / TILE_E)
#define GRID    152
#define LN_EPS  1e-5f

typedef unsigned long long u64;

// ---- packed f32x2 helpers (sm_103a FFMA2 path, PTX-only per SASS_QUICKREF) ----
__device__ __forceinline__ u64 pack2(float x, float y) {
    u64 r;
    asm("mov.b64 %0, {%1, %2};" : "=l"(r) : "r"(__float_as_uint(x)), "r"(__float_as_uint(y)));
    return r;
}
__device__ __forceinline__ u64 dup2(float x) {
    u64 r;
    unsigned u = __float_as_uint(x);
    asm("mov.b64 %0, {%1, %2};" : "=l"(r) : "r"(u), "r"(u));
    return r;
}
__device__ __forceinline__ void fma2(u64 &d, u64 a, u64 b) {
    asm("fma.rn.f32x2 %0, %1, %2, %3;" : "=l"(d) : "l"(a), "l"(b), "l"(d));
}
__device__ __forceinline__ void unpack2(u64 v, float &x, float &y) {
    unsigned lo, hi;
    asm("mov.b64 {%0, %1}, %2;" : "=r"(lo), "=r"(hi) : "l"(v));
    x = __uint_as_float(lo);
    y = __uint_as_float(hi);
}

__device__ __forceinline__ void cp4(float* dst, const float* src, int n, int tid) {
    float4* d4 = (float4*)dst;
    const float4* s4 = (const float4*)src;
    for (int i = tid; i < (n >> 2); i += THREADS) d4[i] = s4[i];
}

// relu -> LayerNorm(64) -> transposed store into xs rows [rowBase + c0 .. +3]
__device__ __forceinline__ void relu_ln_store(
    u64 acc[4][2], const float* __restrict__ bias, const float* __restrict__ gamma,
    const float* __restrict__ beta, float* __restrict__ xs,
    int rowBase, int e0, int c0)
{
    float v[4][4];
#pragma unroll
    for (int e = 0; e < 4; e++) {
        unpack2(acc[e][0], v[e][0], v[e][1]);
        unpack2(acc[e][1], v[e][2], v[e][3]);
    }
    float b0 = bias[c0], b1 = bias[c0 + 1], b2 = bias[c0 + 2], b3 = bias[c0 + 3];
    float s[4], q[4];
#pragma unroll
    for (int e = 0; e < 4; e++) {
        float t0 = fmaxf(v[e][0] + b0, 0.f);
        float t1 = fmaxf(v[e][1] + b1, 0.f);
        float t2 = fmaxf(v[e][2] + b2, 0.f);
        float t3 = fmaxf(v[e][3] + b3, 0.f);
        v[e][0] = t0; v[e][1] = t1; v[e][2] = t2; v[e][3] = t3;
        s[e] = t0 + t1 + t2 + t3;
        q[e] = t0 * t0 + t1 * t1 + t2 * t2 + t3 * t3;
    }
    // 16 threads (same lane%16 group) share one edge's 64 channels
#pragma unroll
    for (int m = 1; m < 16; m <<= 1) {
#pragma unroll
        for (int e = 0; e < 4; e++) {
            s[e] += __shfl_xor_sync(0xffffffffu, s[e], m);
            q[e] += __shfl_xor_sync(0xffffffffu, q[e], m);
        }
    }
    float gm[4] = {gamma[c0], gamma[c0 + 1], gamma[c0 + 2], gamma[c0 + 3]};
    float bt[4] = {beta[c0], beta[c0 + 1], beta[c0 + 2], beta[c0 + 3]};
#pragma unroll
    for (int e = 0; e < 4; e++) {
        float mean = s[e] * (1.f / 64.f);
        float var  = q[e] * (1.f / 64.f) - mean * mean;
        float rstd = rsqrtf(var + LN_EPS);
#pragma unroll
        for (int c = 0; c < 4; c++)
            v[e][c] = (v[e][c] - mean) * rstd * gm[c] + bt[c];
    }
#pragma unroll
    for (int c = 0; c < 4; c++) {
        *(float4*)&xs[(rowBase + c0 + c) * ESTR + e0] =
            make_float4(v[0][c], v[1][c], v[2][c], v[3][c]);
    }
}

__global__ __launch_bounds__(THREADS, 1)
void EdgeModel_48636209660177_kernel(
    const float* __restrict__ src, const float* __restrict__ dst,
    const float* __restrict__ ea,
    const float* __restrict__ W1, const float* __restrict__ b1,
    const float* __restrict__ g1, const float* __restrict__ be1,
    const float* __restrict__ W2, const float* __restrict__ b2,
    const float* __restrict__ g2, const float* __restrict__ be2,
    const float* __restrict__ W3, const float* __restrict__ b3,
    float* __restrict__ out)
{
    extern __shared__ float sm[];
    float* sW1  = sm;                 // 96*64 = 6144
    float* sW2  = sW1 + 6144;         // 160*64 = 10240
    float* sW3  = sW2 + 10240;        // 64*32 = 2048
    float* sb1  = sW3 + 2048;
    float* sg1  = sb1 + 64;
    float* sbe1 = sg1 + 64;
    float* sb2  = sbe1 + 64;
    float* sg2  = sb2 + 64;
    float* sbe2 = sg2 + 64;
    float* sb3  = sbe2 + 64;          // 32
    float* xs   = sb3 + 32;           // 160 rows * ESTR

    const int tid = threadIdx.x;
    cp4(sW1, W1, 6144, tid);
    cp4(sW2, W2, 10240, tid);
    cp4(sW3, W3, 2048, tid);
    cp4(sb1, b1, 64, tid);  cp4(sg1, g1, 64, tid);  cp4(sbe1, be1, 64, tid);
    cp4(sb2, b2, 64, tid);  cp4(sg2, g2, 64, tid);  cp4(sbe2, be2, 64, tid);
    cp4(sb3, b3, 32, tid);

    const int eg = tid >> 4;    // 0..31 -> 4 edges each
    const int cg = tid & 15;    // 0..15 -> 4 cols each (layers 1/2), 2 cols (layer 3)
    const int e0 = eg * 4;
    const int c0 = cg * 4;

    for (int tile = blockIdx.x; tile < NTILES; tile += gridDim.x) {
        const int ebase = tile * TILE_E;
        __syncthreads();   // protect xs rows 64..127 from previous tile's layer-3 reads

        // ---- stage x0 = concat(src,dest,edge_attr) transposed into rows 64..159 ----
#pragma unroll
        for (int t = 0; t < 3; t++) {
            const float* g = (t == 0) ? src : (t == 1) ? dst : ea;
            const int R = 64 + t * 32;
            for (int i = tid; i < TILE_E * 8; i += THREADS) {
                int e = i >> 3, c4 = (i & 7) * 4;
                float4 v = make_float4(0.f, 0.f, 0.f, 0.f);
                if (ebase + e < E_TOTAL)
                    v = *(const float4*)&g[(size_t)(ebase + e) * FX + c4];
                xs[(R + c4 + 0) * ESTR + e] = v.x;
                xs[(R + c4 + 1) * ESTR + e] = v.y;
                xs[(R + c4 + 2) * ESTR + e] = v.z;
                xs[(R + c4 + 3) * ESTR + e] = v.w;
            }
        }
        __syncthreads();

        // ---- layer 1: h1 = LN(relu(x0 @ W1 + b1)) -> rows 0..63 ----
        {
            u64 acc[4][2];
#pragma unroll
            for (int e = 0; e < 4; e++) { acc[e][0] = 0ull; acc[e][1] = 0ull; }
#pragma unroll 4
            for (int k = 0; k < D0; k++) {
                float4 xv = *(const float4*)&xs[(64 + k) * ESTR + e0];
                float4 wv = *(const float4*)&sW1[k * HID + c0];
                u64 w0 = pack2(wv.x, wv.y), w1 = pack2(wv.z, wv.w);
                u64 a;
                a = dup2(xv.x); fma2(acc[0][0], a, w0); fma2(acc[0][1], a, w1);
                a = dup2(xv.y); fma2(acc[1][0], a, w0); fma2(acc[1][1], a, w1);
                a = dup2(xv.z); fma2(acc[2][0], a, w0); fma2(acc[2][1], a, w1);
                a = dup2(xv.w); fma2(acc[3][0], a, w0); fma2(acc[3][1], a, w1);
            }
            relu_ln_store(acc, sb1, sg1, sbe1, xs, 0, e0, c0);
        }
        __syncthreads();

        // ---- layer 2: h2 = LN(relu(concat(h1,x0) @ W2 + b2)) -> rows 64..127 ----
        {
            u64 acc[4][2];
#pragma unroll
            for (int e = 0; e < 4; e++) { acc[e][0] = 0ull; acc[e][1] = 0ull; }
#pragma unroll 4
            for (int k = 0; k < KL2; k++) {
                float4 xv = *(const float4*)&xs[k * ESTR + e0];
                float4 wv = *(const float4*)&sW2[k * HID + c0];
                u64 w0 = pack2(wv.x, wv.y), w1 = pack2(wv.z, wv.w);
                u64 a;
                a = dup2(xv.x); fma2(acc[0][0], a, w0); fma2(acc[0][1], a, w1);
                a = dup2(xv.y); fma2(acc[1][0], a, w0); fma2(acc[1][1], a, w1);
                a = dup2(xv.z); fma2(acc[2][0], a, w0); fma2(acc[2][1], a, w1);
                a = dup2(xv.w); fma2(acc[3][0], a, w0); fma2(acc[3][1], a, w1);
            }
            __syncthreads();   // all reads of rows 0..159 done before overwriting 64..127
            relu_ln_store(acc, sb2, sg2, sbe2, xs, 64, e0, c0);
        }
        __syncthreads();

        // ---- layer 3: out = h2 @ W3 + b3 ----
        {
            const int c0b = cg * 2;
            u64 acc3[4] = {0ull, 0ull, 0ull, 0ull};
#pragma unroll 4
            for (int k = 0; k < HID; k++) {
                float4 xv = *(const float4*)&xs[(64 + k) * ESTR + e0];
                float2 wv = *(const float2*)&sW3[k * OUTC + c0b];
                u64 w = pack2(wv.x, wv.y);
                fma2(acc3[0], dup2(xv.x), w);
                fma2(acc3[1], dup2(xv.y), w);
                fma2(acc3[2], dup2(xv.z), w);
                fma2(acc3[3], dup2(xv.w), w);
            }
            float bx = sb3[c0b], by = sb3[c0b + 1];
#pragma unroll
            for (int e = 0; e < 4; e++) {
                int ge = ebase + e0 + e;
                if (ge < E_TOTAL) {
                    float x, y;
                    unpack2(acc3[e], x, y);
                    *(float2*)&out[(size_t)ge * OUTC + c0b] = make_float2(x + bx, y + by);
                }
            }
        }
    }
}

#define SMEM_BYTES ((6144 + 10240 + 2048 + 64*6 + 32 + 160*ESTR) * (int)sizeof(float))

extern "C" void kernel_launch(void* const* d_in, const int* in_sizes, int n_in,
                              void* d_out, int out_size) {
    (void)in_sizes; (void)n_in; (void)out_size;
    const float* src = (const float*)d_in[0];
    const float* dst = (const float*)d_in[1];
    const float* ea  = (const float*)d_in[2];
    const float* W1  = (const float*)d_in[3];
    const float* b1  = (const float*)d_in[4];
    const float* g1  = (const float*)d_in[5];
    const float* be1 = (const float*)d_in[6];
    const float* W2  = (const float*)d_in[7];
    const float* b2  = (const float*)d_in[8];
    const float* g2  = (const float*)d_in[9];
    const float* be2 = (const float*)d_in[10];
    const float* W3  = (const float*)d_in[11];
    const float* b3  = (const float*)d_in[12];
    float* out = (float*)d_out;

    cudaFuncSetAttribute(EdgeModel_48636209660177_kernel,
                         cudaFuncAttributeMaxDynamicSharedMemorySize, SMEM_BYTES);
    EdgeModel_48636209660177_kernel<<<GRID, THREADS, SMEM_BYTES>>>(
        src, dst, ea, W1, b1, g1, be1, W2, b2, g2, be2, W3, b3, out);
}